// round 2
// baseline (speedup 1.0000x reference)
#include <cuda_runtime.h>

#define NB 256      // batch
#define M 128       // txt positions
#define N 128       // img positions (127 real + 1 synthetic fully-padded)
#define D 1024      // embedding dim
#define BK 32       // GEMM k-tile
#define TP 132      // tile pitch (floats), multiple of 4 for float4 alignment
#define NTHREADS 256

__device__ float g_dist[NB];

struct ShMem {
    float A[N * M];     // A[i*M + j] = exp(-2*cost[j,i]) masked
    float Q[N * M];     // working matrix (also reused as GEMM tile staging)
    float invx[M];
    float invy[N];
    float xmask[M];     // 10000 if padded else 0
    float ymask[N];
    float sigma[M];
    float delta[N];
    float spart[NTHREADS];
    float xl, yl;
};

extern __shared__ __align__(16) char smem_raw[];

__global__ __launch_bounds__(NTHREADS, 1)
void ot_kernel(const float* __restrict__ txt,
               const float* __restrict__ obj,
               const int* __restrict__ txt_num,
               const int* __restrict__ obj_num)
{
    ShMem* sh = reinterpret_cast<ShMem*>(smem_raw);
    const int tid  = threadIdx.x;
    const int lane = tid & 31;
    const int warp = tid >> 5;
    const int b    = blockIdx.x;

    const float* txt_b = txt + (size_t)b * M * D;
    const float* obj_b = obj + (size_t)b * M * D;   // img row i -> obj row i+1

    // ---------------- Phase 0: row norms + masks + lengths ----------------
    for (int r = warp; r < 255; r += 8) {
        const float* p = (r < 128) ? (txt_b + r * D) : (obj_b + (r - 127) * D);
        float ss = 0.f;
        #pragma unroll
        for (int k = 0; k < D; k += 128) {
            float4 v = *reinterpret_cast<const float4*>(p + k + lane * 4);
            ss += v.x * v.x + v.y * v.y + v.z * v.z + v.w * v.w;
        }
        #pragma unroll
        for (int o = 16; o; o >>= 1) ss += __shfl_xor_sync(0xffffffffu, ss, o);
        if (lane == 0) {
            float inv = 1.f / fmaxf(sqrtf(ss), 1e-5f);
            if (r < 128) sh->invx[r] = inv;
            else         sh->invy[r - 128] = inv;
        }
    }
    if (tid == 0) sh->invy[127] = 0.f;   // synthetic padded img slot
    if (tid < 128) {
        sh->xmask[tid] = (txt_num[b * 128 + tid] == 0) ? 1e4f : 0.f;
        float ym = 1e4f;
        if (tid < 127) ym = (obj_num[b * 128 + tid + 1] == 0) ? 1e4f : 0.f;
        sh->ymask[tid] = ym;
    }
    __syncthreads();
    if (tid == 0) {
        float c = 0.f;
        for (int j = 0; j < 128; ++j) c += (sh->xmask[j] == 0.f) ? 1.f : 0.f;
        sh->xl = c;
    }
    if (tid == 1) {
        float c = 0.f;
        for (int i = 0; i < 128; ++i) c += (sh->ymask[i] == 0.f) ? 1.f : 0.f;
        sh->yl = c;
    }
    __syncthreads();

    // ---------------- Phase 1: cost GEMM (128x128x1024, fp32) ----------------
    // thread (tx,ty): i = ty*8+ri (img), j = tx*8+cj (txt)
    float* XsT = sh->Q;              // [BK][TP]  (k-major, txt)
    float* YsT = sh->Q + BK * TP;    // [BK][TP]  (k-major, img)
    const int tx = tid & 15, ty = tid >> 4;

    float acc[8][8];
    #pragma unroll
    for (int r = 0; r < 8; ++r)
        #pragma unroll
        for (int c = 0; c < 8; ++c) acc[r][c] = 0.f;

    for (int kb = 0; kb < D; kb += BK) {
        __syncthreads();
        #pragma unroll
        for (int it = 0; it < 4; ++it) {
            int idx = tid + it * 256;          // 0..1023
            int row = idx >> 3;                // 0..127
            int k4  = (idx & 7) * 4;           // 0,4,..,28
            // X tile (txt), normalized
            float4 xv = *reinterpret_cast<const float4*>(txt_b + row * D + kb + k4);
            float sx = sh->invx[row];
            XsT[(k4 + 0) * TP + row] = xv.x * sx;
            XsT[(k4 + 1) * TP + row] = xv.y * sx;
            XsT[(k4 + 2) * TP + row] = xv.z * sx;
            XsT[(k4 + 3) * TP + row] = xv.w * sx;
            // Y tile (img), normalized; row 127 is zero
            float4 yv = make_float4(0.f, 0.f, 0.f, 0.f);
            float sy = sh->invy[row];
            if (row < 127)
                yv = *reinterpret_cast<const float4*>(obj_b + (row + 1) * D + kb + k4);
            YsT[(k4 + 0) * TP + row] = yv.x * sy;
            YsT[(k4 + 1) * TP + row] = yv.y * sy;
            YsT[(k4 + 2) * TP + row] = yv.z * sy;
            YsT[(k4 + 3) * TP + row] = yv.w * sy;
        }
        __syncthreads();
        #pragma unroll 8
        for (int kk = 0; kk < BK; ++kk) {
            float4 a0 = *reinterpret_cast<const float4*>(&YsT[kk * TP + ty * 8]);
            float4 a1 = *reinterpret_cast<const float4*>(&YsT[kk * TP + ty * 8 + 4]);
            float4 b0 = *reinterpret_cast<const float4*>(&XsT[kk * TP + tx * 8]);
            float4 b1 = *reinterpret_cast<const float4*>(&XsT[kk * TP + tx * 8 + 4]);
            float av[8] = {a0.x, a0.y, a0.z, a0.w, a1.x, a1.y, a1.z, a1.w};
            float bv[8] = {b0.x, b0.y, b0.z, b0.w, b1.x, b1.y, b1.z, b1.w};
            #pragma unroll
            for (int r = 0; r < 8; ++r)
                #pragma unroll
                for (int c = 0; c < 8; ++c) acc[r][c] += av[r] * bv[c];
        }
    }
    __syncthreads();   // all tile reads done before overwriting Q region

    // Epilogue: A = mask ? 0 : exp(-cost/beta), beta=0.5; Q = A
    #pragma unroll
    for (int ri = 0; ri < 8; ++ri) {
        int i = ty * 8 + ri;
        float ypad = sh->ymask[i];
        #pragma unroll
        for (int c4 = 0; c4 < 2; ++c4) {
            float tmp[4];
            #pragma unroll
            for (int u = 0; u < 4; ++u) {
                int cj = c4 * 4 + u;
                int j = tx * 8 + cj;
                float cost = 1.f - acc[ri][cj];
                float a = (ypad > 0.f || sh->xmask[j] > 0.f) ? 0.f : expf(-2.f * cost);
                tmp[u] = a;
            }
            float4 a4 = make_float4(tmp[0], tmp[1], tmp[2], tmp[3]);
            int base = i * M + tx * 8 + c4 * 4;
            *reinterpret_cast<float4*>(&sh->A[base]) = a4;
            *reinterpret_cast<float4*>(&sh->Q[base]) = a4;
        }
    }
    __syncthreads();

    // ---------------- Phase 2: IPOT (50 iterations, k=1) ----------------
    const float xl = sh->xl, yl = sh->yl;
    if (tid < 128) sh->sigma[tid] = (sh->xmask[tid] > 0.f) ? 0.f : (1.f / xl);
    __syncthreads();

    for (int t = 0; t < 50; ++t) {
        // (a) r_i = sum_j Q_ij * sigma_j ; delta_i = 1/(yl*r_i + ymask_i)
        float sg0 = sh->sigma[lane];
        float sg1 = sh->sigma[lane + 32];
        float sg2 = sh->sigma[lane + 64];
        float sg3 = sh->sigma[lane + 96];
        for (int i = warp; i < N; i += 8) {
            const float* q = &sh->Q[i * M];
            float s = q[lane] * sg0 + q[lane + 32] * sg1
                    + q[lane + 64] * sg2 + q[lane + 96] * sg3;
            #pragma unroll
            for (int o = 16; o; o >>= 1) s += __shfl_xor_sync(0xffffffffu, s, o);
            if (lane == 0) sh->delta[i] = 1.f / (yl * s + sh->ymask[i]);
        }
        __syncthreads();
        // (b) s_j = sum_i delta_i * Q_ij ; sigma_j = 1/(xl*s_j + xmask_j)
        {
            int j = tid & 127, h = tid >> 7;
            const float* q  = &sh->Q[(h * 64) * M + j];
            const float* dl = &sh->delta[h * 64];
            float s = 0.f;
            #pragma unroll 8
            for (int i = 0; i < 64; ++i) s += dl[i] * q[i * M];
            sh->spart[tid] = s;
        }
        __syncthreads();
        if (tid < 128) {
            float s = sh->spart[tid] + sh->spart[tid + 128];
            sh->sigma[tid] = 1.f / (xl * s + sh->xmask[tid]);
        }
        __syncthreads();
        // (c) Q <- A * delta_i * Q * sigma_j   (skip on last iter: that Q,delta,sigma define final T)
        if (t < 49) {
            #pragma unroll 4
            for (int e = tid; e < N * M; e += NTHREADS) {
                int i = e >> 7;
                int j = e & 127;
                sh->Q[e] *= sh->A[e] * sh->delta[i] * sh->sigma[j];
            }
            __syncthreads();
        }
    }

    // ---------------- Final: dist_b = sum cost_ij * delta_i * Q_ij * sigma_j ----------------
    float local = 0.f;
    for (int e = tid; e < N * M; e += NTHREADS) {
        float a = sh->A[e];
        if (a > 0.f) {
            int i = e >> 7, j = e & 127;
            float cost = -0.5f * logf(a);
            local += cost * sh->delta[i] * sh->Q[e] * sh->sigma[j];
        }
    }
    __syncthreads();
    sh->spart[tid] = local;
    __syncthreads();
    #pragma unroll
    for (int s = 128; s; s >>= 1) {
        if (tid < s) sh->spart[tid] += sh->spart[tid + s];
        __syncthreads();
    }
    if (tid == 0) g_dist[b] = sh->spart[0];
}

__global__ void finalize_kernel(float* __restrict__ out) {
    __shared__ float sm[NB];
    int t = threadIdx.x;
    sm[t] = g_dist[t];
    __syncthreads();
    #pragma unroll
    for (int s = NB / 2; s; s >>= 1) {
        if (t < s) sm[t] += sm[t + s];
        __syncthreads();
    }
    if (t == 0) out[0] = 0.01f * sm[0];
}

extern "C" void kernel_launch(void* const* d_in, const int* in_sizes, int n_in,
                              void* d_out, int out_size) {
    const float* txt = (const float*)d_in[0];   // entitytxt_vec [256,128,1024] f32
    const float* obj = (const float*)d_in[1];   // object_vec    [256,128,1024] f32
    const int*   tn  = (const int*)d_in[2];     // entitytxt_num [256,128] i32
    const int*   on  = (const int*)d_in[3];     // object_num    [256,128] i32

    size_t shbytes = sizeof(ShMem);
    cudaFuncSetAttribute(ot_kernel, cudaFuncAttributeMaxDynamicSharedMemorySize,
                         (int)shbytes);
    ot_kernel<<<NB, NTHREADS, shbytes>>>(txt, obj, tn, on);
    finalize_kernel<<<1, NB>>>((float*)d_out);
}

// round 3
// speedup vs baseline: 1.0032x; 1.0032x over previous
#include <cuda_runtime.h>

#define NB 256      // batch
#define M 128       // txt positions
#define N 128       // img positions (127 real + 1 synthetic fully-padded)
#define D 1024      // embedding dim
#define BK 32       // GEMM k-tile
#define TP 132      // tile pitch (floats), multiple of 4 for float4 alignment
#define NTHREADS 256

__device__ float g_dist[NB];

struct ShMem {
    float A[N * M];     // A[i*M + j] = exp(-2*cost[j,i]) masked
    float Q[N * M];     // working matrix (also reused as GEMM tile staging)
    float invx[M];
    float invy[N];
    float xmask[M];     // 10000 if padded else 0
    float ymask[N];
    float sigma[M];
    float delta[N];
    float spart[NTHREADS];
    float xl, yl;
};

extern __shared__ __align__(16) char smem_raw[];

__global__ __launch_bounds__(NTHREADS, 1)
void ot_kernel(const float* __restrict__ txt,
               const float* __restrict__ obj,
               const int* __restrict__ txt_num,
               const int* __restrict__ obj_num)
{
    ShMem* sh = reinterpret_cast<ShMem*>(smem_raw);
    const int tid  = threadIdx.x;
    const int lane = tid & 31;
    const int warp = tid >> 5;
    const int b    = blockIdx.x;

    const float* txt_b = txt + (size_t)b * M * D;
    const float* obj_b = obj + (size_t)b * M * D;   // img row i -> obj row i+1

    // ---------------- Phase 0: row norms + masks + lengths ----------------
    for (int r = warp; r < 255; r += 8) {
        const float* p = (r < 128) ? (txt_b + r * D) : (obj_b + (r - 127) * D);
        float ss = 0.f;
        #pragma unroll
        for (int k = 0; k < D; k += 128) {
            float4 v = *reinterpret_cast<const float4*>(p + k + lane * 4);
            ss += v.x * v.x + v.y * v.y + v.z * v.z + v.w * v.w;
        }
        #pragma unroll
        for (int o = 16; o; o >>= 1) ss += __shfl_xor_sync(0xffffffffu, ss, o);
        if (lane == 0) {
            float inv = 1.f / fmaxf(sqrtf(ss), 1e-5f);
            if (r < 128) sh->invx[r] = inv;
            else         sh->invy[r - 128] = inv;
        }
    }
    if (tid == 0) sh->invy[127] = 0.f;   // synthetic padded img slot
    if (tid < 128) {
        sh->xmask[tid] = (txt_num[b * 128 + tid] == 0) ? 1e4f : 0.f;
        float ym = 1e4f;
        if (tid < 127) ym = (obj_num[b * 128 + tid + 1] == 0) ? 1e4f : 0.f;
        sh->ymask[tid] = ym;
    }
    __syncthreads();
    if (tid == 0) {
        float c = 0.f;
        for (int j = 0; j < 128; ++j) c += (sh->xmask[j] == 0.f) ? 1.f : 0.f;
        sh->xl = c;
    }
    if (tid == 1) {
        float c = 0.f;
        for (int i = 0; i < 128; ++i) c += (sh->ymask[i] == 0.f) ? 1.f : 0.f;
        sh->yl = c;
    }
    __syncthreads();

    // ---------------- Phase 1: cost GEMM (128x128x1024, fp32) ----------------
    // thread (tx,ty): i = ty*8+ri (img), j = tx*8+cj (txt)
    float* XsT = sh->Q;              // [BK][TP]  (k-major, txt)
    float* YsT = sh->Q + BK * TP;    // [BK][TP]  (k-major, img)
    const int tx = tid & 15, ty = tid >> 4;

    float acc[8][8];
    #pragma unroll
    for (int r = 0; r < 8; ++r)
        #pragma unroll
        for (int c = 0; c < 8; ++c) acc[r][c] = 0.f;

    for (int kb = 0; kb < D; kb += BK) {
        __syncthreads();
        #pragma unroll
        for (int it = 0; it < 4; ++it) {
            int idx = tid + it * 256;          // 0..1023
            int row = idx >> 3;                // 0..127
            int k4  = (idx & 7) * 4;           // 0,4,..,28
            // X tile (txt), normalized
            float4 xv = *reinterpret_cast<const float4*>(txt_b + row * D + kb + k4);
            float sx = sh->invx[row];
            XsT[(k4 + 0) * TP + row] = xv.x * sx;
            XsT[(k4 + 1) * TP + row] = xv.y * sx;
            XsT[(k4 + 2) * TP + row] = xv.z * sx;
            XsT[(k4 + 3) * TP + row] = xv.w * sx;
            // Y tile (img), normalized; row 127 is zero
            float4 yv = make_float4(0.f, 0.f, 0.f, 0.f);
            float sy = sh->invy[row];
            if (row < 127)
                yv = *reinterpret_cast<const float4*>(obj_b + (row + 1) * D + kb + k4);
            YsT[(k4 + 0) * TP + row] = yv.x * sy;
            YsT[(k4 + 1) * TP + row] = yv.y * sy;
            YsT[(k4 + 2) * TP + row] = yv.z * sy;
            YsT[(k4 + 3) * TP + row] = yv.w * sy;
        }
        __syncthreads();
        #pragma unroll 8
        for (int kk = 0; kk < BK; ++kk) {
            float4 a0 = *reinterpret_cast<const float4*>(&YsT[kk * TP + ty * 8]);
            float4 a1 = *reinterpret_cast<const float4*>(&YsT[kk * TP + ty * 8 + 4]);
            float4 b0 = *reinterpret_cast<const float4*>(&XsT[kk * TP + tx * 8]);
            float4 b1 = *reinterpret_cast<const float4*>(&XsT[kk * TP + tx * 8 + 4]);
            float av[8] = {a0.x, a0.y, a0.z, a0.w, a1.x, a1.y, a1.z, a1.w};
            float bv[8] = {b0.x, b0.y, b0.z, b0.w, b1.x, b1.y, b1.z, b1.w};
            #pragma unroll
            for (int r = 0; r < 8; ++r)
                #pragma unroll
                for (int c = 0; c < 8; ++c) acc[r][c] += av[r] * bv[c];
        }
    }
    __syncthreads();   // all tile reads done before overwriting Q region

    // Epilogue: A = mask ? 0 : exp(-cost/beta), beta=0.5; Q = A
    #pragma unroll
    for (int ri = 0; ri < 8; ++ri) {
        int i = ty * 8 + ri;
        float ypad = sh->ymask[i];
        #pragma unroll
        for (int c4 = 0; c4 < 2; ++c4) {
            float tmp[4];
            #pragma unroll
            for (int u = 0; u < 4; ++u) {
                int cj = c4 * 4 + u;
                int j = tx * 8 + cj;
                float cost = 1.f - acc[ri][cj];
                float a = (ypad > 0.f || sh->xmask[j] > 0.f) ? 0.f : expf(-2.f * cost);
                tmp[u] = a;
            }
            float4 a4 = make_float4(tmp[0], tmp[1], tmp[2], tmp[3]);
            int base = i * M + tx * 8 + c4 * 4;
            *reinterpret_cast<float4*>(&sh->A[base]) = a4;
            *reinterpret_cast<float4*>(&sh->Q[base]) = a4;
        }
    }
    __syncthreads();

    // ---------------- Phase 2: IPOT (50 iterations, k=1) ----------------
    const float xl = sh->xl, yl = sh->yl;
    if (tid < 128) sh->sigma[tid] = (sh->xmask[tid] > 0.f) ? 0.f : (1.f / xl);
    __syncthreads();

    for (int t = 0; t < 50; ++t) {
        // (a) r_i = sum_j Q_ij * sigma_j ; delta_i = 1/(yl*r_i + ymask_i)
        float sg0 = sh->sigma[lane];
        float sg1 = sh->sigma[lane + 32];
        float sg2 = sh->sigma[lane + 64];
        float sg3 = sh->sigma[lane + 96];
        for (int i = warp; i < N; i += 8) {
            const float* q = &sh->Q[i * M];
            float s = q[lane] * sg0 + q[lane + 32] * sg1
                    + q[lane + 64] * sg2 + q[lane + 96] * sg3;
            #pragma unroll
            for (int o = 16; o; o >>= 1) s += __shfl_xor_sync(0xffffffffu, s, o);
            if (lane == 0) sh->delta[i] = 1.f / (yl * s + sh->ymask[i]);
        }
        __syncthreads();
        // (b) s_j = sum_i delta_i * Q_ij ; sigma_j = 1/(xl*s_j + xmask_j)
        {
            int j = tid & 127, h = tid >> 7;
            const float* q  = &sh->Q[(h * 64) * M + j];
            const float* dl = &sh->delta[h * 64];
            float s = 0.f;
            #pragma unroll 8
            for (int i = 0; i < 64; ++i) s += dl[i] * q[i * M];
            sh->spart[tid] = s;
        }
        __syncthreads();
        if (tid < 128) {
            float s = sh->spart[tid] + sh->spart[tid + 128];
            sh->sigma[tid] = 1.f / (xl * s + sh->xmask[tid]);
        }
        __syncthreads();
        // (c) Q <- A * delta_i * Q * sigma_j   (skip on last iter: that Q,delta,sigma define final T)
        if (t < 49) {
            #pragma unroll 4
            for (int e = tid; e < N * M; e += NTHREADS) {
                int i = e >> 7;
                int j = e & 127;
                sh->Q[e] *= sh->A[e] * sh->delta[i] * sh->sigma[j];
            }
            __syncthreads();
        }
    }

    // ---------------- Final: dist_b = sum cost_ij * delta_i * Q_ij * sigma_j ----------------
    float local = 0.f;
    for (int e = tid; e < N * M; e += NTHREADS) {
        float a = sh->A[e];
        if (a > 0.f) {
            int i = e >> 7, j = e & 127;
            float cost = -0.5f * logf(a);
            local += cost * sh->delta[i] * sh->Q[e] * sh->sigma[j];
        }
    }
    __syncthreads();
    sh->spart[tid] = local;
    __syncthreads();
    #pragma unroll
    for (int s = 128; s; s >>= 1) {
        if (tid < s) sh->spart[tid] += sh->spart[tid + s];
        __syncthreads();
    }
    if (tid == 0) g_dist[b] = sh->spart[0];
}

__global__ void finalize_kernel(float* __restrict__ out) {
    __shared__ float sm[NB];
    int t = threadIdx.x;
    sm[t] = g_dist[t];
    __syncthreads();
    #pragma unroll
    for (int s = NB / 2; s; s >>= 1) {
        if (t < s) sm[t] += sm[t + s];
        __syncthreads();
    }
    if (t == 0) out[0] = 0.01f * sm[0];
}

extern "C" void kernel_launch(void* const* d_in, const int* in_sizes, int n_in,
                              void* d_out, int out_size) {
    const float* txt = (const float*)d_in[0];   // entitytxt_vec [256,128,1024] f32
    const float* obj = (const float*)d_in[1];   // object_vec    [256,128,1024] f32
    const int*   tn  = (const int*)d_in[2];     // entitytxt_num [256,128] i32
    const int*   on  = (const int*)d_in[3];     // object_num    [256,128] i32

    size_t shbytes = sizeof(ShMem);
    cudaFuncSetAttribute(ot_kernel, cudaFuncAttributeMaxDynamicSharedMemorySize,
                         (int)shbytes);
    ot_kernel<<<NB, NTHREADS, shbytes>>>(txt, obj, tn, on);
    finalize_kernel<<<1, NB>>>((float*)d_out);
}